// round 13
// baseline (speedup 1.0000x reference)
#include <cuda_runtime.h>
#include <cuda_bf16.h>
#include <cuda_fp16.h>
#include <math.h>
#include <stdint.h>

#define NATOMS 524288
#define DD     256
#define NB     16384
#define MSTEPS 6

// ---------------- persistent device scratch (no allocs allowed) -------------
__device__ float g_c[NB * DD];                 // 16 MB
__device__ __half g_X16[(size_t)NATOMS * DD];  // 268 MB fp16 copy of X
__device__ __nv_bfloat16 g_Ahi[NB * 512];      // A = [h,r] hi part (h lives here)
__device__ __nv_bfloat16 g_Alo[NB * 512];      // A lo part
__device__ __nv_bfloat16 g_UThi[1024 * 512];   // U^T (gate-permuted cols): [n'][k]
__device__ __nv_bfloat16 g_UTlo[1024 * 512];
__device__ float g_bperm[1024];                // permuted bias
__device__ int   g_seg[NB + 1];

// ---------------- helpers -----------------------------------------------------
__device__ __forceinline__ uint32_t smem_u32(const void* p) {
    uint32_t a;
    asm("{ .reg .u64 t; cvta.to.shared.u64 t, %1; cvt.u32.u64 %0, t; }" : "=r"(a) : "l"(p));
    return a;
}
__device__ __forceinline__ void cp_async16(uint32_t dst, const void* src) {
    asm volatile("cp.async.cg.shared.global [%0], [%1], 16;" :: "r"(dst), "l"(src) : "memory");
}
__device__ __forceinline__ void ldm_x4(uint32_t* r, uint32_t addr) {
    asm volatile("ldmatrix.sync.aligned.m8n8.x4.shared.b16 {%0,%1,%2,%3}, [%4];"
                 : "=r"(r[0]), "=r"(r[1]), "=r"(r[2]), "=r"(r[3]) : "r"(addr));
}
__device__ __forceinline__ void mma16816(float* d, const uint32_t* a, const uint32_t* b) {
    asm volatile(
        "mma.sync.aligned.m16n8k16.row.col.f32.bf16.bf16.f32 "
        "{%0,%1,%2,%3}, {%4,%5,%6,%7}, {%8,%9}, {%0,%1,%2,%3};"
        : "+f"(d[0]), "+f"(d[1]), "+f"(d[2]), "+f"(d[3])
        : "r"(a[0]), "r"(a[1]), "r"(a[2]), "r"(a[3]), "r"(b[0]), "r"(b[1]));
}
__device__ __forceinline__ uint32_t swz(int row, int seg) {
    return (uint32_t)(row * 64 + ((seg ^ ((row >> 1) & 3)) << 4));
}
__device__ __forceinline__ float fsig(float x) { return 1.f / (1.f + __expf(-x)); }
__device__ __forceinline__ float ftanh(float x) { return 2.f / (1.f + __expf(-2.f * x)) - 1.f; }

__device__ __forceinline__ void ld8h(const __half* p, float4& x0, float4& x1) {
    uint4 v = *(const uint4*)p;
    const __half2* h = (const __half2*)&v;
    float2 a = __half22float2(h[0]);
    float2 b = __half22float2(h[1]);
    float2 c = __half22float2(h[2]);
    float2 d = __half22float2(h[3]);
    x0 = make_float4(a.x, a.y, b.x, b.y);
    x1 = make_float4(c.x, c.y, d.x, d.y);
}
__device__ __forceinline__ void st8h(__half* p, float4 x0, float4 x1) {
    __half2 h[4];
    h[0] = __floats2half2_rn(x0.x, x0.y);
    h[1] = __floats2half2_rn(x0.z, x0.w);
    h[2] = __floats2half2_rn(x1.x, x1.y);
    h[3] = __floats2half2_rn(x1.z, x1.w);
    *(uint4*)p = *(uint4*)h;
}

// ---------------- segment offsets --------------------------------------------
__global__ void segstart_kernel(const int* __restrict__ split) {
    int j = blockIdx.x * blockDim.x + threadIdx.x;
    if (j > NB) return;
    int lo = 0, hi = NATOMS;
    while (lo < hi) { int mid = (lo + hi) >> 1; if (split[mid] < j) lo = mid + 1; else hi = mid; }
    g_seg[j] = lo;
}

// ---------------- prep U: transpose + bf16 split + gate-permute cols, once ----
__global__ void prep_U_kernel(const float* __restrict__ U, const float* __restrict__ bias) {
    __shared__ float tile[32][33];
    int bx = blockIdx.x;
    int by = blockIdx.y;
    int tx = threadIdx.x & 31, ty = threadIdx.x >> 5;
    #pragma unroll
    for (int j = 0; j < 4; j++) {
        int k = by * 32 + ty + j * 8;
        int n = bx * 32 + tx;
        tile[ty + j * 8][tx] = U[(size_t)k * 1024 + n];
    }
    __syncthreads();
    #pragma unroll
    for (int j = 0; j < 4; j++) {
        int n = bx * 32 + ty + j * 8;
        int k = by * 32 + tx;
        int gg = n >> 8, d = n & 255;
        int n2 = ((d >> 5) << 7) + (gg << 5) + (d & 31);
        float v = tile[tx][ty + j * 8];
        __nv_bfloat16 hi = __float2bfloat16(v);
        float lo = v - __bfloat162float(hi);
        g_UThi[(size_t)n2 * 512 + k] = hi;
        g_UTlo[(size_t)n2 * 512 + k] = __float2bfloat16(lo);
    }
    if (by == 0 && ty == 0) {
        int n = bx * 32 + tx;
        int gg = n >> 8, d = n & 255;
        int n2 = ((d >> 5) << 7) + (gg << 5) + (d & 31);
        g_bperm[n2] = bias[n];
    }
}

// ---------------- attention: one warp per molecule (R11, measured-best) -------
__device__ __forceinline__ float dot8(float4 a0, float4 a1, float4 h0, float4 h1) {
    return a0.x*h0.x + a0.y*h0.y + a0.z*h0.z + a0.w*h0.w
         + a1.x*h1.x + a1.y*h1.y + a1.z*h1.z + a1.w*h1.w;
}
__device__ __forceinline__ void acc8(float4& A0, float4& A1, float wgt,
                                     const float4& x0, const float4& x1) {
    A0.x += wgt * x0.x; A0.y += wgt * x0.y; A0.z += wgt * x0.z; A0.w += wgt * x0.w;
    A1.x += wgt * x1.x; A1.y += wgt * x1.y; A1.z += wgt * x1.z; A1.w += wgt * x1.w;
}
__device__ __forceinline__ void add8(float4& A0, float4& A1,
                                     const float4& x0, const float4& x1) {
    A0.x += x0.x; A0.y += x0.y; A0.z += x0.z; A0.w += x0.w;
    A1.x += x1.x; A1.y += x1.y; A1.z += x1.z; A1.w += x1.w;
}

__global__ void step0_kernel(const float* __restrict__ X) {
    int gw   = (blockIdx.x * blockDim.x + threadIdx.x) >> 5;
    int lane = threadIdx.x & 31;
    if (gw >= NB) return;
    int s = g_seg[gw];
    int e = g_seg[gw + 1];

    float4 A0 = make_float4(0.f, 0.f, 0.f, 0.f);
    float4 A1 = make_float4(0.f, 0.f, 0.f, 0.f);
    for (int i = s; i < e; i++) {
        const float4* p0 = (const float4*)(X + (size_t)i * DD + lane * 8);
        float4 x0 = p0[0], x1 = p0[1];
        add8(A0, A1, x0, x1);
        st8h(g_X16 + (size_t)i * DD + lane * 8, x0, x1);   // fused conversion
    }
    float inv = (e > s) ? (1.0f / (float)(e - s)) : 0.f;
    float r[8] = {A0.x*inv, A0.y*inv, A0.z*inv, A0.w*inv,
                  A1.x*inv, A1.y*inv, A1.z*inv, A1.w*inv};
    __nv_bfloat16 hi8[8], lo8[8];
    #pragma unroll
    for (int t = 0; t < 8; t++) {
        hi8[t] = __float2bfloat16(r[t]);
        lo8[t] = __float2bfloat16(r[t] - __bfloat162float(hi8[t]));
    }
    *(uint4*)(g_Ahi + (size_t)gw * 512 + 256 + lane * 8) = *(uint4*)hi8;
    *(uint4*)(g_Alo + (size_t)gw * 512 + 256 + lane * 8) = *(uint4*)lo8;
}

__global__ void attn_kernel(float* __restrict__ out, int mode) {
    int gw   = (blockIdx.x * blockDim.x + threadIdx.x) >> 5;
    int lane = threadIdx.x & 31;
    if (gw >= NB) return;
    int s = g_seg[gw];
    int e = g_seg[gw + 1];

    uint4 vh = *(const uint4*)(g_Ahi + (size_t)gw * 512 + lane * 8);
    uint4 vl = *(const uint4*)(g_Alo + (size_t)gw * 512 + lane * 8);
    const __nv_bfloat16* hb = (const __nv_bfloat16*)&vh;
    const __nv_bfloat16* lb = (const __nv_bfloat16*)&vl;
    float hv[8];
    #pragma unroll
    for (int t = 0; t < 8; t++)
        hv[t] = __bfloat162float(hb[t]) + __bfloat162float(lb[t]);
    float4 h0 = make_float4(hv[0], hv[1], hv[2], hv[3]);
    float4 h1 = make_float4(hv[4], hv[5], hv[6], hv[7]);

    float4 A0 = make_float4(0.f, 0.f, 0.f, 0.f);
    float4 A1 = make_float4(0.f, 0.f, 0.f, 0.f);
    float sumexp = 0.f;

    const __half* Xp = g_X16;
    int i = s;
    for (; i + 4 <= e; i += 4) {
        float4 xa0, xa1, xb0, xb1, xc0, xc1, xd0, xd1;
        ld8h(Xp + (size_t)(i    ) * DD + lane * 8, xa0, xa1);
        ld8h(Xp + (size_t)(i + 1) * DD + lane * 8, xb0, xb1);
        ld8h(Xp + (size_t)(i + 2) * DD + lane * 8, xc0, xc1);
        ld8h(Xp + (size_t)(i + 3) * DD + lane * 8, xd0, xd1);
        float pa = dot8(xa0, xa1, h0, h1);
        float pb = dot8(xb0, xb1, h0, h1);
        float pc = dot8(xc0, xc1, h0, h1);
        float pd = dot8(xd0, xd1, h0, h1);
        #pragma unroll
        for (int m = 16; m; m >>= 1) {
            pa += __shfl_xor_sync(0xffffffffu, pa, m);
            pb += __shfl_xor_sync(0xffffffffu, pb, m);
            pc += __shfl_xor_sync(0xffffffffu, pc, m);
            pd += __shfl_xor_sync(0xffffffffu, pd, m);
        }
        float wa = __expf(pa), wb = __expf(pb), wc = __expf(pc), wd = __expf(pd);
        sumexp += (wa + wb) + (wc + wd);
        acc8(A0, A1, wa, xa0, xa1); acc8(A0, A1, wb, xb0, xb1);
        acc8(A0, A1, wc, xc0, xc1); acc8(A0, A1, wd, xd0, xd1);
    }
    for (; i < e; i++) {
        float4 xa0, xa1;
        ld8h(Xp + (size_t)i * DD + lane * 8, xa0, xa1);
        float pa = dot8(xa0, xa1, h0, h1);
        #pragma unroll
        for (int m = 16; m; m >>= 1) pa += __shfl_xor_sync(0xffffffffu, pa, m);
        float wa = __expf(pa);
        sumexp += wa;
        acc8(A0, A1, wa, xa0, xa1);
    }

    float inv = (e > s) ? (1.0f / sumexp) : 0.f;
    float r[8] = {A0.x*inv, A0.y*inv, A0.z*inv, A0.w*inv,
                  A1.x*inv, A1.y*inv, A1.z*inv, A1.w*inv};

    if (mode == 0) {
        __nv_bfloat16 hi8[8], lo8[8];
        #pragma unroll
        for (int t = 0; t < 8; t++) {
            hi8[t] = __float2bfloat16(r[t]);
            lo8[t] = __float2bfloat16(r[t] - __bfloat162float(hi8[t]));
        }
        *(uint4*)(g_Ahi + (size_t)gw * 512 + 256 + lane * 8) = *(uint4*)hi8;
        *(uint4*)(g_Alo + (size_t)gw * 512 + 256 + lane * 8) = *(uint4*)lo8;
    } else {
        float* op = out + (size_t)gw * 512 + 256 + lane * 8;
        *(float4*)(op)     = make_float4(r[0], r[1], r[2], r[3]);
        *(float4*)(op + 4) = make_float4(r[4], r[5], r[6], r[7]);
    }
}

// ---------------- HMMA GEMM + fused LSTM gates --------------------------------
// 2-stage ring @ 64KB/CTA -> 3 CTAs/SM (24 warps) for more HMMA latency cover.
#define BK       32
#define KTILES   16
#define SA_HI    0
#define SA_LO    8192
#define SB_HI    16384
#define SB_LO    24576
#define STAGE_B  32768
#define SMEM_TOT (2 * STAGE_B)
#define ZS_STRIDE 128

__device__ __forceinline__ void load_stage(uint32_t sdst, int kbase,
                                           int block_row, int block_col, int tid) {
    #pragma unroll
    for (int halfp = 0; halfp < 2; halfp++) {
        int c   = tid + halfp * 256;
        int row = c >> 2;
        int seg = c & 3;
        uint32_t doff = swz(row, seg);
        size_t aoff = (size_t)(block_row + row) * 512 + kbase + seg * 8;
        size_t boff = (size_t)(block_col + row) * 512 + kbase + seg * 8;
        cp_async16(sdst + SA_HI + doff, g_Ahi  + aoff);
        cp_async16(sdst + SA_LO + doff, g_Alo  + aoff);
        cp_async16(sdst + SB_HI + doff, g_UThi + boff);
        cp_async16(sdst + SB_LO + doff, g_UTlo + boff);
    }
}

__global__ void __launch_bounds__(256, 3)
lstm_gemm_fused_kernel(float* __restrict__ out, int write_out, int kt_start, int czero) {
    extern __shared__ char smem[];
    uint32_t smem_base = smem_u32(smem);
    int tid  = threadIdx.x;
    int wid  = tid >> 5;
    int lane = tid & 31;
    int warp_m = wid & 3;
    int warp_n = wid >> 2;
    int block_row = blockIdx.y * 128;
    int block_col = blockIdx.x * 128;

    float acc[2][8][4];
    #pragma unroll
    for (int i = 0; i < 2; i++)
        #pragma unroll
        for (int j = 0; j < 8; j++)
            #pragma unroll
            for (int t = 0; t < 4; t++) acc[i][j][t] = 0.f;

    int a_row = warp_m * 32 + (lane & 15);
    int a_segbit = (lane >> 4);
    int b_row = warp_n * 64 + ((lane >> 4) << 3) + (lane & 7);
    int b_segbit = ((lane >> 3) & 1);

    load_stage(smem_base + (kt_start & 1) * STAGE_B, kt_start * BK,
               block_row, block_col, tid);
    asm volatile("cp.async.commit_group;" ::: "memory");

    for (int kt = kt_start; kt < KTILES; kt++) {
        if (kt + 1 < KTILES) {
            load_stage(smem_base + ((kt + 1) & 1) * STAGE_B, (kt + 1) * BK,
                       block_row, block_col, tid);
            asm volatile("cp.async.commit_group;" ::: "memory");
            asm volatile("cp.async.wait_group 1;" ::: "memory");
        } else {
            asm volatile("cp.async.wait_group 0;" ::: "memory");
        }
        __syncthreads();

        uint32_t sbase = smem_base + (kt & 1) * STAGE_B;
        #pragma unroll
        for (int ksub = 0; ksub < 2; ksub++) {
            uint32_t a_hi[2][4], a_lo[2][4];
            #pragma unroll
            for (int mt = 0; mt < 2; mt++) {
                int rrow = a_row + mt * 16;
                uint32_t off = swz(rrow, ksub * 2 + a_segbit);
                ldm_x4(a_hi[mt], sbase + SA_HI + off);
                ldm_x4(a_lo[mt], sbase + SA_LO + off);
            }
            uint32_t b_hi[4][4], b_lo[4][4];
            #pragma unroll
            for (int nt2 = 0; nt2 < 4; nt2++) {
                int rrow = b_row + nt2 * 16;
                uint32_t off = swz(rrow, ksub * 2 + b_segbit);
                ldm_x4(b_hi[nt2], sbase + SB_HI + off);
                ldm_x4(b_lo[nt2], sbase + SB_LO + off);
            }
            #pragma unroll
            for (int mt = 0; mt < 2; mt++) {
                #pragma unroll
                for (int nt = 0; nt < 8; nt++) {
                    const uint32_t* bh = &b_hi[nt >> 1][(nt & 1) * 2];
                    const uint32_t* bl = &b_lo[nt >> 1][(nt & 1) * 2];
                    mma16816(acc[mt][nt], a_hi[mt], bh);
                    mma16816(acc[mt][nt], a_hi[mt], bl);
                    mma16816(acc[mt][nt], a_lo[mt], bh);
                }
            }
        }
        __syncthreads();
    }

    // ---- epilogue: acc -> SMEM z-tile, then fused LSTM gates ----
    float* zs = (float*)smem;
    #pragma unroll
    for (int nt = 0; nt < 8; nt++) {
        int c = warp_n * 64 + nt * 8 + (lane & 3) * 2;
        #pragma unroll
        for (int mt = 0; mt < 2; mt++) {
            int r0 = warp_m * 32 + mt * 16 + (lane >> 2);
            *(float2*)&zs[r0 * ZS_STRIDE + c]       = make_float2(acc[mt][nt][0], acc[mt][nt][1]);
            *(float2*)&zs[(r0 + 8) * ZS_STRIDE + c] = make_float2(acc[mt][nt][2], acc[mt][nt][3]);
        }
    }
    __syncthreads();

    int dloc = tid & 31;
    int d_global = blockIdx.x * 32 + dloc;
    float bi = g_bperm[block_col + dloc];
    float bf = g_bperm[block_col + 32 + dloc];
    float bo = g_bperm[block_col + 64 + dloc];
    float bg = g_bperm[block_col + 96 + dloc];

    #pragma unroll
    for (int j = 0; j < 16; j++) {
        int row = (tid >> 5) + j * 8;
        const float* zr = zs + row * ZS_STRIDE;
        float ig = fsig(zr[dloc]      + bi);
        float fg = fsig(zr[32 + dloc] + bf);
        float og = fsig(zr[64 + dloc] + bo);
        float gg = ftanh(zr[96 + dloc] + bg);
        int grow = block_row + row;
        size_t idx = (size_t)grow * 256 + d_global;
        float c = czero ? (ig * gg) : (fg * g_c[idx] + ig * gg);
        g_c[idx] = c;
        float h = og * ftanh(c);
        __nv_bfloat16 hi = __float2bfloat16(h);
        g_Ahi[(size_t)grow * 512 + d_global] = hi;
        g_Alo[(size_t)grow * 512 + d_global] = __float2bfloat16(h - __bfloat162float(hi));
        if (write_out)
            out[(size_t)grow * 512 + d_global] = h;
    }
}

// ------------------------------------------------------------------------------
extern "C" void kernel_launch(void* const* d_in, const int* in_sizes, int n_in,
                              void* d_out, int out_size) {
    (void)in_sizes; (void)n_in; (void)out_size;
    const float* X     = (const float*)d_in[0];   // [NATOMS, 256]
    const int*   split = (const int*)  d_in[1];   // [NATOMS]
    const float* U     = (const float*)d_in[2];   // [512, 1024]
    const float* bias  = (const float*)d_in[3];   // [1024]
    float* out = (float*)d_out;                   // [NB, 512]

    cudaFuncSetAttribute(lstm_gemm_fused_kernel,
                         cudaFuncAttributeMaxDynamicSharedMemorySize, SMEM_TOT);

    segstart_kernel<<<(NB + 1 + 255) / 256, 256>>>(split);
    {
        dim3 tg(32, 16);
        prep_U_kernel<<<tg, 256>>>(U, bias);
    }

    dim3 gemm_grid(8, 128);
    int attn_blocks = NB / 8;               // 1 warp per molecule (R11 best)

    for (int step = 0; step < MSTEPS; step++) {
        int last  = (step == MSTEPS - 1);
        int first = (step == 0);
        if (first)
            step0_kernel<<<attn_blocks, 256>>>(X);   // mean pass + fp16 X cache
        else
            attn_kernel<<<attn_blocks, 256>>>(out, last ? 1 : 0);
        if (!last) {
            lstm_gemm_fused_kernel<<<gemm_grid, 256, SMEM_TOT>>>(
                out,
                (step == MSTEPS - 2) ? 1 : 0,
                first ? 8 : 0,
                first ? 1 : 0);
        }
    }
}

// round 14
// speedup vs baseline: 1.5642x; 1.5642x over previous
#include <cuda_runtime.h>
#include <cuda_fp16.h>
#include <math.h>
#include <stdint.h>

#define NATOMS 524288
#define DD     256
#define NB     16384
#define MSTEPS 6

// ---------------- persistent device scratch (no allocs allowed) -------------
__device__ float g_c[NB * DD];                 // 16 MB
__device__ __half g_X16[(size_t)NATOMS * DD];  // 268 MB fp16 copy of X
__device__ __half g_Ahi[NB * 512];             // A = [h,r] fp16 hi (h lives here)
__device__ __half g_Alo[NB * 512];             // A fp16 lo (residual)
__device__ __half g_UT16[1024 * 512];          // U^T (gate-permuted cols), fp16
__device__ float g_bperm[1024];                // permuted bias
__device__ int   g_seg[NB + 1];

// ---------------- helpers -----------------------------------------------------
__device__ __forceinline__ uint32_t smem_u32(const void* p) {
    uint32_t a;
    asm("{ .reg .u64 t; cvta.to.shared.u64 t, %1; cvt.u32.u64 %0, t; }" : "=r"(a) : "l"(p));
    return a;
}
__device__ __forceinline__ void cp_async16(uint32_t dst, const void* src) {
    asm volatile("cp.async.cg.shared.global [%0], [%1], 16;" :: "r"(dst), "l"(src) : "memory");
}
__device__ __forceinline__ void ldm_x4(uint32_t* r, uint32_t addr) {
    asm volatile("ldmatrix.sync.aligned.m8n8.x4.shared.b16 {%0,%1,%2,%3}, [%4];"
                 : "=r"(r[0]), "=r"(r[1]), "=r"(r[2]), "=r"(r[3]) : "r"(addr));
}
__device__ __forceinline__ void mma16816h(float* d, const uint32_t* a, const uint32_t* b) {
    asm volatile(
        "mma.sync.aligned.m16n8k16.row.col.f32.f16.f16.f32 "
        "{%0,%1,%2,%3}, {%4,%5,%6,%7}, {%8,%9}, {%0,%1,%2,%3};"
        : "+f"(d[0]), "+f"(d[1]), "+f"(d[2]), "+f"(d[3])
        : "r"(a[0]), "r"(a[1]), "r"(a[2]), "r"(a[3]), "r"(b[0]), "r"(b[1]));
}
__device__ __forceinline__ uint32_t swz(int row, int seg) {
    return (uint32_t)(row * 64 + ((seg ^ ((row >> 1) & 3)) << 4));
}
__device__ __forceinline__ float fsig(float x) { return 1.f / (1.f + __expf(-x)); }
__device__ __forceinline__ float ftanh(float x) { return 2.f / (1.f + __expf(-2.f * x)) - 1.f; }

__device__ __forceinline__ void ld8h(const __half* p, float4& x0, float4& x1) {
    uint4 v = *(const uint4*)p;
    const __half2* h = (const __half2*)&v;
    float2 a = __half22float2(h[0]);
    float2 b = __half22float2(h[1]);
    float2 c = __half22float2(h[2]);
    float2 d = __half22float2(h[3]);
    x0 = make_float4(a.x, a.y, b.x, b.y);
    x1 = make_float4(c.x, c.y, d.x, d.y);
}
__device__ __forceinline__ void st8h(__half* p, float4 x0, float4 x1) {
    __half2 h[4];
    h[0] = __floats2half2_rn(x0.x, x0.y);
    h[1] = __floats2half2_rn(x0.z, x0.w);
    h[2] = __floats2half2_rn(x1.x, x1.y);
    h[3] = __floats2half2_rn(x1.z, x1.w);
    *(uint4*)p = *(uint4*)h;
}

// ---------------- segment offsets --------------------------------------------
__global__ void segstart_kernel(const int* __restrict__ split) {
    int j = blockIdx.x * blockDim.x + threadIdx.x;
    if (j > NB) return;
    int lo = 0, hi = NATOMS;
    while (lo < hi) { int mid = (lo + hi) >> 1; if (split[mid] < j) lo = mid + 1; else hi = mid; }
    g_seg[j] = lo;
}

// ---------------- prep U: transpose + fp16 + gate-permute cols, once ----------
// source col n = g*256 + d  ->  dest col n' = (d>>5)*128 + g*32 + (d&31)
__global__ void prep_U_kernel(const float* __restrict__ U, const float* __restrict__ bias) {
    __shared__ float tile[32][33];
    int bx = blockIdx.x;
    int by = blockIdx.y;
    int tx = threadIdx.x & 31, ty = threadIdx.x >> 5;
    #pragma unroll
    for (int j = 0; j < 4; j++) {
        int k = by * 32 + ty + j * 8;
        int n = bx * 32 + tx;
        tile[ty + j * 8][tx] = U[(size_t)k * 1024 + n];
    }
    __syncthreads();
    #pragma unroll
    for (int j = 0; j < 4; j++) {
        int n = bx * 32 + ty + j * 8;
        int k = by * 32 + tx;
        int gg = n >> 8, d = n & 255;
        int n2 = ((d >> 5) << 7) + (gg << 5) + (d & 31);
        g_UT16[(size_t)n2 * 512 + k] = __float2half_rn(tile[tx][ty + j * 8]);
    }
    if (by == 0 && ty == 0) {
        int n = bx * 32 + tx;
        int gg = n >> 8, d = n & 255;
        int n2 = ((d >> 5) << 7) + (gg << 5) + (d & 31);
        g_bperm[n2] = bias[n];
    }
}

// ---------------- attention: one warp per molecule (R11 structure) ------------
__device__ __forceinline__ float dot8(float4 a0, float4 a1, float4 h0, float4 h1) {
    return a0.x*h0.x + a0.y*h0.y + a0.z*h0.z + a0.w*h0.w
         + a1.x*h1.x + a1.y*h1.y + a1.z*h1.z + a1.w*h1.w;
}
__device__ __forceinline__ void acc8(float4& A0, float4& A1, float wgt,
                                     const float4& x0, const float4& x1) {
    A0.x += wgt * x0.x; A0.y += wgt * x0.y; A0.z += wgt * x0.z; A0.w += wgt * x0.w;
    A1.x += wgt * x1.x; A1.y += wgt * x1.y; A1.z += wgt * x1.z; A1.w += wgt * x1.w;
}
__device__ __forceinline__ void add8(float4& A0, float4& A1,
                                     const float4& x0, const float4& x1) {
    A0.x += x0.x; A0.y += x0.y; A0.z += x0.z; A0.w += x0.w;
    A1.x += x1.x; A1.y += x1.y; A1.z += x1.z; A1.w += x1.w;
}
// write 8 floats as fp16 hi/lo pair into A row
__device__ __forceinline__ void write_A_hilo(__half* dhi, __half* dlo, const float* v) {
    __half hi8[8], lo8[8];
    #pragma unroll
    for (int t = 0; t < 8; t++) {
        hi8[t] = __float2half_rn(v[t]);
        lo8[t] = __float2half_rn(v[t] - __half2float(hi8[t]));
    }
    *(uint4*)dhi = *(uint4*)hi8;
    *(uint4*)dlo = *(uint4*)lo8;
}

__global__ void step0_kernel(const float* __restrict__ X) {
    int gw   = (blockIdx.x * blockDim.x + threadIdx.x) >> 5;
    int lane = threadIdx.x & 31;
    if (gw >= NB) return;
    int s = g_seg[gw];
    int e = g_seg[gw + 1];

    float4 A0 = make_float4(0.f, 0.f, 0.f, 0.f);
    float4 A1 = make_float4(0.f, 0.f, 0.f, 0.f);
    for (int i = s; i < e; i++) {
        const float4* p0 = (const float4*)(X + (size_t)i * DD + lane * 8);
        float4 x0 = p0[0], x1 = p0[1];
        add8(A0, A1, x0, x1);
        st8h(g_X16 + (size_t)i * DD + lane * 8, x0, x1);   // fused conversion
    }
    float inv = (e > s) ? (1.0f / (float)(e - s)) : 0.f;
    float r[8] = {A0.x*inv, A0.y*inv, A0.z*inv, A0.w*inv,
                  A1.x*inv, A1.y*inv, A1.z*inv, A1.w*inv};
    write_A_hilo(g_Ahi + (size_t)gw * 512 + 256 + lane * 8,
                 g_Alo + (size_t)gw * 512 + 256 + lane * 8, r);
}

__global__ void attn_kernel(float* __restrict__ out, int mode) {
    int gw   = (blockIdx.x * blockDim.x + threadIdx.x) >> 5;
    int lane = threadIdx.x & 31;
    if (gw >= NB) return;
    int s = g_seg[gw];
    int e = g_seg[gw + 1];

    // reconstruct h = hi + lo from the fp16 split (err ~2^-22)
    float4 hh0, hh1, hl0, hl1;
    ld8h(g_Ahi + (size_t)gw * 512 + lane * 8, hh0, hh1);
    ld8h(g_Alo + (size_t)gw * 512 + lane * 8, hl0, hl1);
    float4 h0 = make_float4(hh0.x + hl0.x, hh0.y + hl0.y, hh0.z + hl0.z, hh0.w + hl0.w);
    float4 h1 = make_float4(hh1.x + hl1.x, hh1.y + hl1.y, hh1.z + hl1.z, hh1.w + hl1.w);

    float4 A0 = make_float4(0.f, 0.f, 0.f, 0.f);
    float4 A1 = make_float4(0.f, 0.f, 0.f, 0.f);
    float sumexp = 0.f;

    const __half* Xp = g_X16;
    int i = s;
    for (; i + 4 <= e; i += 4) {
        float4 xa0, xa1, xb0, xb1, xc0, xc1, xd0, xd1;
        ld8h(Xp + (size_t)(i    ) * DD + lane * 8, xa0, xa1);
        ld8h(Xp + (size_t)(i + 1) * DD + lane * 8, xb0, xb1);
        ld8h(Xp + (size_t)(i + 2) * DD + lane * 8, xc0, xc1);
        ld8h(Xp + (size_t)(i + 3) * DD + lane * 8, xd0, xd1);
        float pa = dot8(xa0, xa1, h0, h1);
        float pb = dot8(xb0, xb1, h0, h1);
        float pc = dot8(xc0, xc1, h0, h1);
        float pd = dot8(xd0, xd1, h0, h1);
        #pragma unroll
        for (int m = 16; m; m >>= 1) {
            pa += __shfl_xor_sync(0xffffffffu, pa, m);
            pb += __shfl_xor_sync(0xffffffffu, pb, m);
            pc += __shfl_xor_sync(0xffffffffu, pc, m);
            pd += __shfl_xor_sync(0xffffffffu, pd, m);
        }
        float wa = __expf(pa), wb = __expf(pb), wc = __expf(pc), wd = __expf(pd);
        sumexp += (wa + wb) + (wc + wd);
        acc8(A0, A1, wa, xa0, xa1); acc8(A0, A1, wb, xb0, xb1);
        acc8(A0, A1, wc, xc0, xc1); acc8(A0, A1, wd, xd0, xd1);
    }
    for (; i < e; i++) {
        float4 xa0, xa1;
        ld8h(Xp + (size_t)i * DD + lane * 8, xa0, xa1);
        float pa = dot8(xa0, xa1, h0, h1);
        #pragma unroll
        for (int m = 16; m; m >>= 1) pa += __shfl_xor_sync(0xffffffffu, pa, m);
        float wa = __expf(pa);
        sumexp += wa;
        acc8(A0, A1, wa, xa0, xa1);
    }

    float inv = (e > s) ? (1.0f / sumexp) : 0.f;
    float r[8] = {A0.x*inv, A0.y*inv, A0.z*inv, A0.w*inv,
                  A1.x*inv, A1.y*inv, A1.z*inv, A1.w*inv};

    if (mode == 0) {
        write_A_hilo(g_Ahi + (size_t)gw * 512 + 256 + lane * 8,
                     g_Alo + (size_t)gw * 512 + 256 + lane * 8, r);
    } else {
        float* op = out + (size_t)gw * 512 + 256 + lane * 8;
        *(float4*)(op)     = make_float4(r[0], r[1], r[2], r[3]);
        *(float4*)(op + 4) = make_float4(r[4], r[5], r[6], r[7]);
    }
}

// ---------------- HMMA GEMM + fused LSTM gates --------------------------------
// fp16 2-term split: z = Ahi*U16 + Alo*U16. CTA 128x128, 3-stage ring @24KB,
// 72KB total -> 2 CTAs/SM (R8-proven config), one sync per k-tile.
#define BK       32
#define KTILES   16
#define SA_HI    0
#define SA_LO    8192
#define SB_U     16384
#define STAGE_B  24576
#define SMEM_TOT (3 * STAGE_B)
#define ZS_STRIDE 128

__device__ __forceinline__ void load_stage(uint32_t sdst, int kbase,
                                           int block_row, int block_col, int tid) {
    #pragma unroll
    for (int halfp = 0; halfp < 2; halfp++) {
        int c   = tid + halfp * 256;
        int row = c >> 2;
        int seg = c & 3;
        uint32_t doff = swz(row, seg);
        size_t aoff = (size_t)(block_row + row) * 512 + kbase + seg * 8;
        size_t boff = (size_t)(block_col + row) * 512 + kbase + seg * 8;
        cp_async16(sdst + SA_HI + doff, g_Ahi  + aoff);
        cp_async16(sdst + SA_LO + doff, g_Alo  + aoff);
        cp_async16(sdst + SB_U  + doff, g_UT16 + boff);
    }
}

__global__ void __launch_bounds__(256, 2)
lstm_gemm_fused_kernel(float* __restrict__ out, int write_out, int kt_start, int czero) {
    extern __shared__ char smem[];
    uint32_t smem_base = smem_u32(smem);
    int tid  = threadIdx.x;
    int wid  = tid >> 5;
    int lane = tid & 31;
    int warp_m = wid & 3;
    int warp_n = wid >> 2;
    int block_row = blockIdx.y * 128;
    int block_col = blockIdx.x * 128;

    float acc[2][8][4];
    #pragma unroll
    for (int i = 0; i < 2; i++)
        #pragma unroll
        for (int j = 0; j < 8; j++)
            #pragma unroll
            for (int t = 0; t < 4; t++) acc[i][j][t] = 0.f;

    int a_row = warp_m * 32 + (lane & 15);
    int a_segbit = (lane >> 4);
    int b_row = warp_n * 64 + ((lane >> 4) << 3) + (lane & 7);
    int b_segbit = ((lane >> 3) & 1);

    load_stage(smem_base + (kt_start % 3) * STAGE_B, kt_start * BK,
               block_row, block_col, tid);
    asm volatile("cp.async.commit_group;" ::: "memory");
    load_stage(smem_base + ((kt_start + 1) % 3) * STAGE_B, (kt_start + 1) * BK,
               block_row, block_col, tid);
    asm volatile("cp.async.commit_group;" ::: "memory");

    for (int kt = kt_start; kt < KTILES; kt++) {
        if (kt + 1 < KTILES) asm volatile("cp.async.wait_group 1;" ::: "memory");
        else                 asm volatile("cp.async.wait_group 0;" ::: "memory");
        __syncthreads();
        if (kt + 2 < KTILES) {
            load_stage(smem_base + ((kt + 2) % 3) * STAGE_B, (kt + 2) * BK,
                       block_row, block_col, tid);
            asm volatile("cp.async.commit_group;" ::: "memory");
        }

        uint32_t sbase = smem_base + (kt % 3) * STAGE_B;
        #pragma unroll
        for (int ksub = 0; ksub < 2; ksub++) {
            uint32_t a_hi[2][4], a_lo[2][4];
            #pragma unroll
            for (int mt = 0; mt < 2; mt++) {
                int rrow = a_row + mt * 16;
                uint32_t off = swz(rrow, ksub * 2 + a_segbit);
                ldm_x4(a_hi[mt], sbase + SA_HI + off);
                ldm_x4(a_lo[mt], sbase + SA_LO + off);
            }
            uint32_t b[4][4];
            #pragma unroll
            for (int nt2 = 0; nt2 < 4; nt2++) {
                int rrow = b_row + nt2 * 16;
                uint32_t off = swz(rrow, ksub * 2 + b_segbit);
                ldm_x4(b[nt2], sbase + SB_U + off);
            }
            #pragma unroll
            for (int mt = 0; mt < 2; mt++) {
                #pragma unroll
                for (int nt = 0; nt < 8; nt++) {
                    const uint32_t* bp = &b[nt >> 1][(nt & 1) * 2];
                    mma16816h(acc[mt][nt], a_hi[mt], bp);
                    mma16816h(acc[mt][nt], a_lo[mt], bp);
                }
            }
        }
    }

    // ---- epilogue: acc -> SMEM z-tile, then fused LSTM gates ----
    __syncthreads();
    float* zs = (float*)smem;
    #pragma unroll
    for (int nt = 0; nt < 8; nt++) {
        int c = warp_n * 64 + nt * 8 + (lane & 3) * 2;
        #pragma unroll
        for (int mt = 0; mt < 2; mt++) {
            int r0 = warp_m * 32 + mt * 16 + (lane >> 2);
            *(float2*)&zs[r0 * ZS_STRIDE + c]       = make_float2(acc[mt][nt][0], acc[mt][nt][1]);
            *(float2*)&zs[(r0 + 8) * ZS_STRIDE + c] = make_float2(acc[mt][nt][2], acc[mt][nt][3]);
        }
    }
    __syncthreads();

    int dloc = tid & 31;
    int d_global = blockIdx.x * 32 + dloc;
    float bi = g_bperm[block_col + dloc];
    float bf = g_bperm[block_col + 32 + dloc];
    float bo = g_bperm[block_col + 64 + dloc];
    float bg = g_bperm[block_col + 96 + dloc];

    #pragma unroll
    for (int j = 0; j < 16; j++) {
        int row = (tid >> 5) + j * 8;
        const float* zr = zs + row * ZS_STRIDE;
        float ig = fsig(zr[dloc]      + bi);
        float fg = fsig(zr[32 + dloc] + bf);
        float og = fsig(zr[64 + dloc] + bo);
        float gg = ftanh(zr[96 + dloc] + bg);
        int grow = block_row + row;
        size_t idx = (size_t)grow * 256 + d_global;
        float c = czero ? (ig * gg) : (fg * g_c[idx] + ig * gg);
        g_c[idx] = c;
        float h = og * ftanh(c);
        __half hi = __float2half_rn(h);
        g_Ahi[(size_t)grow * 512 + d_global] = hi;
        g_Alo[(size_t)grow * 512 + d_global] = __float2half_rn(h - __half2float(hi));
        if (write_out)
            out[(size_t)grow * 512 + d_global] = h;
    }
}

// ------------------------------------------------------------------------------
extern "C" void kernel_launch(void* const* d_in, const int* in_sizes, int n_in,
                              void* d_out, int out_size) {
    (void)in_sizes; (void)n_in; (void)out_size;
    const float* X     = (const float*)d_in[0];   // [NATOMS, 256]
    const int*   split = (const int*)  d_in[1];   // [NATOMS]
    const float* U     = (const float*)d_in[2];   // [512, 1024]
    const float* bias  = (const float*)d_in[3];   // [1024]
    float* out = (float*)d_out;                   // [NB, 512]

    cudaFuncSetAttribute(lstm_gemm_fused_kernel,
                         cudaFuncAttributeMaxDynamicSharedMemorySize, SMEM_TOT);

    segstart_kernel<<<(NB + 1 + 255) / 256, 256>>>(split);
    {
        dim3 tg(32, 16);
        prep_U_kernel<<<tg, 256>>>(U, bias);
    }

    dim3 gemm_grid(8, 128);
    int attn_blocks = NB / 8;               // 1 warp per molecule (R11 best)

    for (int step = 0; step < MSTEPS; step++) {
        int last  = (step == MSTEPS - 1);
        int first = (step == 0);
        if (first)
            step0_kernel<<<attn_blocks, 256>>>(X);   // mean pass + fp16 X cache
        else
            attn_kernel<<<attn_blocks, 256>>>(out, last ? 1 : 0);
        if (!last) {
            lstm_gemm_fused_kernel<<<gemm_grid, 256, SMEM_TOT>>>(
                out,
                (step == MSTEPS - 2) ? 1 : 0,
                first ? 8 : 0,
                first ? 1 : 0);
        }
    }
}